// round 1
// baseline (speedup 1.0000x reference)
#include <cuda_runtime.h>
#include <math.h>
#include <stdint.h>

// ---------------- problem constants ----------------
#define NN      20000      // nodes
#define FEAT    128
#define E0      100000     // undirected edges
#define EDG     200000     // directed (doubled)
#define NRBF    20
#define NCONV   3
#define CUTOFF  20.0f
#define PI_F    3.14159265358979323846f

#define NF      (NN*FEAT)          // 2,560,000
#define N3F     (NN*384)           // 7,680,000

// ---------------- device scratch (no cudaMalloc allowed) ----------------
__device__ float g_sA[NF];
__device__ float g_sB[NF];
__device__ float g_vA[3*NF];
__device__ float g_vB[3*NF];
__device__ float g_phi[N3F];
__device__ float g_hid[NF];
__device__ float g_uv[3*NF];
__device__ float g_vv[3*NF];
__device__ float g_xcat[NN*256];
__device__ float g_am[N3F];
__device__ float g_unit[EDG*3];
__device__ float g_rbf[EDG*NRBF];
__device__ float g_env[EDG];
__device__ int   g_ei[EDG];
__device__ int   g_ej[EDG];

// ---------------- small utility kernels ----------------
__global__ void copy4_kernel(float4* __restrict__ dst, const float4* __restrict__ src, int n4) {
    int i = blockIdx.x * blockDim.x + threadIdx.x;
    if (i < n4) dst[i] = src[i];
}
__global__ void zero4_kernel(float4* __restrict__ dst, int n4) {
    int i = blockIdx.x * blockDim.x + threadIdx.x;
    if (i < n4) dst[i] = make_float4(0.f,0.f,0.f,0.f);
}

// ---------------- edge geometry precompute ----------------
__global__ void edge_geom_kernel(const float* __restrict__ xyz, const int* __restrict__ nbr,
                                 float* __restrict__ unit, float* __restrict__ rbf,
                                 float* __restrict__ env, int* __restrict__ ei, int* __restrict__ ej) {
    int e = blockIdx.x * blockDim.x + threadIdx.x;
    if (e >= EDG) return;
    int p = (e < E0) ? e : (e - E0);
    int a = nbr[p*2], b = nbr[p*2+1];
    int i = (e < E0) ? a : b;
    int j = (e < E0) ? b : a;
    float dx = xyz[j*3+0] - xyz[i*3+0];
    float dy = xyz[j*3+1] - xyz[i*3+1];
    float dz = xyz[j*3+2] - xyz[i*3+2];
    float d  = sqrtf(dx*dx + dy*dy + dz*dz);
    float invd = 1.0f / d;
    unit[e*3+0] = dx*invd; unit[e*3+1] = dy*invd; unit[e*3+2] = dz*invd;
    #pragma unroll
    for (int k = 0; k < NRBF; k++)
        rbf[e*NRBF + k] = sinf((float)(k+1) * PI_F * d / CUTOFF) * invd;
    env[e] = (d < CUTOFF) ? 0.5f * (cosf(PI_F * d / CUTOFF) + 1.0f) : 0.0f;
    ei[e] = i; ej[e] = j;
}

// ---------------- generic fp32 tiled GEMM: C = act(A @ W^T + b) ----------------
// A:(N,K) row-major, W:(M,K) row-major, C:(N,M). blockDim=256, 64x64 tile, 4x4/thread.
template<bool SILU>
__global__ void gemm_kernel(const float* __restrict__ A, size_t aStride,
                            const float* __restrict__ W,
                            const float* __restrict__ bias,
                            float* __restrict__ C, size_t cStride,
                            int N, int M, int K) {
    __shared__ float As[16][64];
    __shared__ float Ws[16][64];
    const int tid = threadIdx.x;
    const int tx = tid & 15, ty = tid >> 4;
    const int rowBase = blockIdx.y * 64;
    const int colBase = blockIdx.x * 64;
    A += (size_t)blockIdx.z * aStride;
    C += (size_t)blockIdx.z * cStride;

    const int lr = tid >> 2;          // 0..63
    const int lk = (tid & 3) * 4;     // 0,4,8,12

    float acc[4][4];
    #pragma unroll
    for (int m = 0; m < 4; m++)
        #pragma unroll
        for (int n = 0; n < 4; n++) acc[m][n] = 0.f;

    for (int k0 = 0; k0 < K; k0 += 16) {
        int r = rowBase + lr;
        float4 av = (r < N) ? *(const float4*)&A[(size_t)r*K + k0 + lk]
                            : make_float4(0.f,0.f,0.f,0.f);
        As[lk+0][lr] = av.x; As[lk+1][lr] = av.y; As[lk+2][lr] = av.z; As[lk+3][lr] = av.w;
        int c = colBase + lr;
        float4 wv = (c < M) ? *(const float4*)&W[(size_t)c*K + k0 + lk]
                            : make_float4(0.f,0.f,0.f,0.f);
        Ws[lk+0][lr] = wv.x; Ws[lk+1][lr] = wv.y; Ws[lk+2][lr] = wv.z; Ws[lk+3][lr] = wv.w;
        __syncthreads();
        #pragma unroll
        for (int kk = 0; kk < 16; kk++) {
            float4 a4 = *(const float4*)&As[kk][ty*4];
            float4 b4 = *(const float4*)&Ws[kk][tx*4];
            float av_[4] = {a4.x, a4.y, a4.z, a4.w};
            float bv_[4] = {b4.x, b4.y, b4.z, b4.w};
            #pragma unroll
            for (int m = 0; m < 4; m++)
                #pragma unroll
                for (int n = 0; n < 4; n++)
                    acc[m][n] += av_[m] * bv_[n];
        }
        __syncthreads();
    }

    #pragma unroll
    for (int m = 0; m < 4; m++) {
        int r = rowBase + ty*4 + m;
        if (r >= N) continue;
        #pragma unroll
        for (int n = 0; n < 4; n++) {
            int c = colBase + tx*4 + n;
            if (c >= M) continue;
            float val = acc[m][n] + (bias ? bias[c] : 0.f);
            if (SILU) val = val / (1.f + expf(-val));
            C[(size_t)r*M + c] = val;
        }
    }
}

// ---------------- edge message: w_s, inv, scatter-add ----------------
// blockDim = 256 => 2 edge-slots of 128 threads each. dist_W staged in smem (padded).
__global__ void edge_msg_kernel(const float* __restrict__ phi,
                                const float* __restrict__ v_old,
                                const float* __restrict__ distW,
                                const float* __restrict__ distb,
                                const int* __restrict__ ei, const int* __restrict__ ej,
                                const float* __restrict__ unit, const float* __restrict__ rbf,
                                const float* __restrict__ env,
                                float* __restrict__ s_acc, float* __restrict__ v_acc) {
    __shared__ float dw[384*21];
    __shared__ float db[384];
    const int tid = threadIdx.x;
    for (int idx = tid; idx < 384*NRBF; idx += 256)
        dw[(idx/NRBF)*21 + (idx%NRBF)] = distW[idx];
    for (int idx = tid; idx < 384; idx += 256) db[idx] = distb[idx];
    __syncthreads();

    const int slot = tid >> 7;   // 0 or 1
    const int f    = tid & 127;
    for (int e = blockIdx.x*2 + slot; e < EDG; e += gridDim.x*2) {
        int i = ei[e], j = ej[e];
        float rb[NRBF];
        #pragma unroll
        for (int k = 0; k < NRBF; k++) rb[k] = rbf[e*NRBF + k];
        float ev = env[e];
        float u0 = unit[e*3+0], u1 = unit[e*3+1], u2 = unit[e*3+2];
        float inv[3];
        #pragma unroll
        for (int c = 0; c < 3; c++) {
            int ch = c*128 + f;
            const float* w = &dw[ch*21];
            float acc = db[ch];
            #pragma unroll
            for (int k = 0; k < NRBF; k++) acc += rb[k] * w[k];
            inv[c] = phi[(size_t)j*384 + ch] * (acc * ev);
        }
        atomicAdd(&s_acc[(size_t)i*128 + f], inv[1]);
        #pragma unroll
        for (int d = 0; d < 3; d++) {
            float vj = v_old[(size_t)d*NF + (size_t)j*128 + f];
            float ud = (d == 0) ? u0 : ((d == 1) ? u1 : u2);
            float dv = inv[2]*ud + inv[0]*vj;
            atomicAdd(&v_acc[(size_t)d*NF + (size_t)i*128 + f], dv);
        }
    }
}

// ---------------- xcat = [s, ||v_v||] ----------------
__global__ void xcat_kernel(const float* __restrict__ s, const float* __restrict__ vv,
                            float* __restrict__ xcat) {
    int idx = blockIdx.x * blockDim.x + threadIdx.x;
    if (idx >= NF) return;
    int n = idx >> 7, f = idx & 127;
    float a = vv[idx], b = vv[NF + idx], c = vv[2*NF + idx];
    xcat[(size_t)n*256 + f]       = s[idx];
    xcat[(size_t)n*256 + 128 + f] = sqrtf(a*a + b*b + c*c);
}

// ---------------- final gated update (in place) ----------------
__global__ void update_kernel(const float* __restrict__ uv, const float* __restrict__ vv,
                              const float* __restrict__ am,
                              float* __restrict__ s, float* __restrict__ v) {
    int idx = blockIdx.x * blockDim.x + threadIdx.x;
    if (idx >= NF) return;
    int n = idx >> 7, f = idx & 127;
    float dot = uv[idx]*vv[idx] + uv[NF+idx]*vv[NF+idx] + uv[2*NF+idx]*vv[2*NF+idx];
    float a0 = am[(size_t)n*384 + f];
    float a1 = am[(size_t)n*384 + 128 + f];
    float a2 = am[(size_t)n*384 + 256 + f];
    s[idx] += dot * a1 + a2;
    #pragma unroll
    for (int d = 0; d < 3; d++)
        v[(size_t)d*NF + idx] += uv[(size_t)d*NF + idx] * a0;
}

// ---------------- pack output: s flat, then v as (N,128,3) ----------------
__global__ void output_kernel(const float* __restrict__ s, const float* __restrict__ v,
                              float* __restrict__ out) {
    int idx = blockIdx.x * blockDim.x + threadIdx.x;
    if (idx >= NF) return;
    int n = idx >> 7, f = idx & 127;
    out[idx] = s[idx];
    #pragma unroll
    for (int d = 0; d < 3; d++)
        out[(size_t)NF + (size_t)n*384 + f*3 + d] = v[(size_t)d*NF + idx];
}

// ---------------- host orchestration ----------------
extern "C" void kernel_launch(void* const* d_in, const int* in_sizes, int n_in,
                              void* d_out, int out_size) {
    const float* xyz    = (const float*)d_in[0];
    const int*   nbr    = (const int*)  d_in[1];
    const float* cg_s   = (const float*)d_in[2];
    const float* msg_W1 = (const float*)d_in[3];
    const float* msg_b1 = (const float*)d_in[4];
    const float* msg_W2 = (const float*)d_in[5];
    const float* msg_b2 = (const float*)d_in[6];
    const float* dist_W = (const float*)d_in[7];
    const float* dist_b = (const float*)d_in[8];
    const float* upd_U  = (const float*)d_in[9];
    const float* upd_V  = (const float*)d_in[10];
    const float* upd_sW1= (const float*)d_in[11];
    const float* upd_sb1= (const float*)d_in[12];
    const float* upd_sW2= (const float*)d_in[13];
    const float* upd_sb2= (const float*)d_in[14];
    float* out = (float*)d_out;

    float *sA, *sB, *vA, *vB, *phi, *hid, *uv, *vv, *xcat, *am, *unit, *rbf, *env;
    int *ei, *ej;
    cudaGetSymbolAddress((void**)&sA,   g_sA);
    cudaGetSymbolAddress((void**)&sB,   g_sB);
    cudaGetSymbolAddress((void**)&vA,   g_vA);
    cudaGetSymbolAddress((void**)&vB,   g_vB);
    cudaGetSymbolAddress((void**)&phi,  g_phi);
    cudaGetSymbolAddress((void**)&hid,  g_hid);
    cudaGetSymbolAddress((void**)&uv,   g_uv);
    cudaGetSymbolAddress((void**)&vv,   g_vv);
    cudaGetSymbolAddress((void**)&xcat, g_xcat);
    cudaGetSymbolAddress((void**)&am,   g_am);
    cudaGetSymbolAddress((void**)&unit, g_unit);
    cudaGetSymbolAddress((void**)&rbf,  g_rbf);
    cudaGetSymbolAddress((void**)&env,  g_env);
    cudaGetSymbolAddress((void**)&ei,   g_ei);
    cudaGetSymbolAddress((void**)&ej,   g_ej);

    const int TPB = 256;
    // init state: s <- cg_s, v <- 0
    copy4_kernel<<<(NF/4 + TPB-1)/TPB, TPB>>>((float4*)sA, (const float4*)cg_s, NF/4);
    zero4_kernel<<<(3*NF/4 + TPB-1)/TPB, TPB>>>((float4*)vA, 3*NF/4);
    // edge geometry
    edge_geom_kernel<<<(EDG + TPB-1)/TPB, TPB>>>(xyz, nbr, unit, rbf, env, ei, ej);

    const int RT = (NN + 63) / 64;   // 313 row tiles
    float* s_cur = sA; float* s_nxt = sB;
    float* v_cur = vA; float* v_nxt = vB;

    for (int l = 0; l < NCONV; l++) {
        // phi = silu(s @ W1^T + b1) @ W2^T + b2
        gemm_kernel<true ><<<dim3(2, RT, 1), TPB>>>(s_cur, 0, msg_W1 + (size_t)l*FEAT*FEAT,
                                                    msg_b1 + (size_t)l*FEAT, hid, 0, NN, FEAT, FEAT);
        gemm_kernel<false><<<dim3(6, RT, 1), TPB>>>(hid, 0, msg_W2 + (size_t)l*384*FEAT,
                                                    msg_b2 + (size_t)l*384, phi, 0, NN, 384, FEAT);
        // accumulators = current state
        copy4_kernel<<<(NF/4 + TPB-1)/TPB, TPB>>>((float4*)s_nxt, (const float4*)s_cur, NF/4);
        copy4_kernel<<<(3*NF/4 + TPB-1)/TPB, TPB>>>((float4*)v_nxt, (const float4*)v_cur, 3*NF/4);
        // edge messages + scatter
        edge_msg_kernel<<<1184, TPB>>>(phi, v_cur,
                                       dist_W + (size_t)l*384*NRBF, dist_b + (size_t)l*384,
                                       ei, ej, unit, rbf, env, s_nxt, v_nxt);
        // u_v, v_v (batched over 3 spatial dims)
        gemm_kernel<false><<<dim3(2, RT, 3), TPB>>>(v_nxt, (size_t)NF, upd_U + (size_t)l*FEAT*FEAT,
                                                    nullptr, uv, (size_t)NF, NN, FEAT, FEAT);
        gemm_kernel<false><<<dim3(2, RT, 3), TPB>>>(v_nxt, (size_t)NF, upd_V + (size_t)l*FEAT*FEAT,
                                                    nullptr, vv, (size_t)NF, NN, FEAT, FEAT);
        // xcat = [s, ||v_v||]
        xcat_kernel<<<(NF + TPB-1)/TPB, TPB>>>(s_nxt, vv, xcat);
        // a = silu(xcat @ sW1^T + sb1) @ sW2^T + sb2
        gemm_kernel<true ><<<dim3(2, RT, 1), TPB>>>(xcat, 0, upd_sW1 + (size_t)l*FEAT*256,
                                                    upd_sb1 + (size_t)l*FEAT, hid, 0, NN, FEAT, 256);
        gemm_kernel<false><<<dim3(6, RT, 1), TPB>>>(hid, 0, upd_sW2 + (size_t)l*384*FEAT,
                                                    upd_sb2 + (size_t)l*384, am, 0, NN, 384, FEAT);
        // gated update (in place on s_nxt / v_nxt)
        update_kernel<<<(NF + TPB-1)/TPB, TPB>>>(uv, vv, am, s_nxt, v_nxt);

        // swap
        float* t;
        t = s_cur; s_cur = s_nxt; s_nxt = t;
        t = v_cur; v_cur = v_nxt; v_nxt = t;
    }

    output_kernel<<<(NF + TPB-1)/TPB, TPB>>>(s_cur, v_cur, out);
}

// round 3
// speedup vs baseline: 1.1092x; 1.1092x over previous
#include <cuda_runtime.h>
#include <math.h>
#include <stdint.h>

// ---------------- problem constants ----------------
#define NN      20000      // nodes
#define FEAT    128
#define E0      100000     // undirected edges
#define EDG     200000     // directed (doubled)
#define NRBF    20
#define NCONV   3
#define CUTOFF  20.0f
#define PI_F    3.14159265358979323846f

#define NF      (NN*FEAT)          // 2,560,000
#define N3F     (NN*384)           // 7,680,000

// ---------------- device scratch (no cudaMalloc allowed) ----------------
__device__ float g_sA[NF];
__device__ float g_sB[NF];
__device__ float g_vA[3*NF];
__device__ float g_vB[3*NF];
__device__ float g_phi[N3F];
__device__ float g_hid[NF];
__device__ float g_uv[3*NF];
__device__ float g_vv[3*NF];
__device__ float g_xcat[NN*256];
__device__ float g_am[N3F];
__device__ float g_unit[EDG*3];
__device__ float g_rbf[EDG*NRBF];
__device__ float g_env[EDG];
__device__ int   g_ei[EDG];
__device__ int   g_ej[EDG];

// ---------------- helpers ----------------
__device__ __forceinline__ float tf32_rna(float x) {
    uint32_t u; asm("cvt.rna.tf32.f32 %0, %1;" : "=r"(u) : "f"(x));
    return __uint_as_float(u);
}
__device__ __forceinline__ void mma_tf32(float* c, const uint32_t* a, uint32_t b0, uint32_t b1) {
    asm volatile(
        "mma.sync.aligned.m16n8k8.row.col.f32.tf32.tf32.f32 "
        "{%0,%1,%2,%3}, {%4,%5,%6,%7}, {%8,%9}, {%0,%1,%2,%3};"
        : "+f"(c[0]), "+f"(c[1]), "+f"(c[2]), "+f"(c[3])
        : "r"(a[0]), "r"(a[1]), "r"(a[2]), "r"(a[3]), "r"(b0), "r"(b1));
}

// ---------------- small utility kernels ----------------
__global__ void copy4_kernel(float4* __restrict__ dst, const float4* __restrict__ src, int n4) {
    int i = blockIdx.x * blockDim.x + threadIdx.x;
    if (i < n4) dst[i] = src[i];
}
__global__ void zero4_kernel(float4* __restrict__ dst, int n4) {
    int i = blockIdx.x * blockDim.x + threadIdx.x;
    if (i < n4) dst[i] = make_float4(0.f,0.f,0.f,0.f);
}

// ---------------- edge geometry precompute ----------------
__global__ void edge_geom_kernel(const float* __restrict__ xyz, const int* __restrict__ nbr,
                                 float* __restrict__ unit, float* __restrict__ rbf,
                                 float* __restrict__ env, int* __restrict__ ei, int* __restrict__ ej) {
    int e = blockIdx.x * blockDim.x + threadIdx.x;
    if (e >= EDG) return;
    int p = (e < E0) ? e : (e - E0);
    int a = nbr[p*2], b = nbr[p*2+1];
    int i = (e < E0) ? a : b;
    int j = (e < E0) ? b : a;
    float dx = xyz[j*3+0] - xyz[i*3+0];
    float dy = xyz[j*3+1] - xyz[i*3+1];
    float dz = xyz[j*3+2] - xyz[i*3+2];
    float d  = sqrtf(dx*dx + dy*dy + dz*dz);
    float invd = 1.0f / d;
    unit[e*3+0] = dx*invd; unit[e*3+1] = dy*invd; unit[e*3+2] = dz*invd;
    #pragma unroll
    for (int k = 0; k < NRBF; k++)
        rbf[e*NRBF + k] = sinf((float)(k+1) * PI_F * d / CUTOFF) * invd;
    env[e] = (d < CUTOFF) ? 0.5f * (cosf(PI_F * d / CUTOFF) + 1.0f) : 0.0f;
    ei[e] = i; ej[e] = j;
}

// =====================================================================
// mma.sync TF32x3 GEMM:  C = act(A @ W^T + b)
// A:(Nrows,K) fp32 row-major, W:(Mcols,K) fp32 row-major, C:(Nrows,Mcols).
// CTA tile 128x128, 8 warps (4 row x 2 col), warp tile 32x64.
// 3xTF32: D = Ah*Bh + Ah*Bl + Al*Bh (fp32-class accuracy on tensor pipe).
// =====================================================================
#define PITCH 20
template<bool SILU>
__global__ void __launch_bounds__(256)
mma_gemm_kernel(const float* __restrict__ A, size_t aStride,
                const float* __restrict__ W,
                const float* __restrict__ bias,
                float* __restrict__ C, size_t cStride,
                int Nrows, int Mcols, int K) {
    __shared__ float Ah[128][PITCH];
    __shared__ float Al[128][PITCH];
    __shared__ float Bh[128][PITCH];
    __shared__ float Bl[128][PITCH];

    const int tid = threadIdx.x;
    const int wid = tid >> 5;
    const int lid = tid & 31;
    const int tq  = lid >> 2;     // 0..7
    const int tr  = lid & 3;      // 0..3
    const int warpRow = (wid & 3) * 32;
    const int warpCol = (wid >> 2) * 64;
    const int rowBase = blockIdx.y * 128;
    const int colBase = blockIdx.x * 128;
    A += (size_t)blockIdx.z * aStride;
    C += (size_t)blockIdx.z * cStride;
    const float* Wt = W + (size_t)colBase * K;

    float acc[2][8][4];
    #pragma unroll
    for (int mf = 0; mf < 2; mf++)
        #pragma unroll
        for (int nf = 0; nf < 8; nf++)
            #pragma unroll
            for (int u = 0; u < 4; u++) acc[mf][nf][u] = 0.f;

    const int ldRow0 = tid >> 2;        // 0..63
    const int ldQ    = (tid & 3) * 4;   // 0,4,8,12

    for (int k0 = 0; k0 < K; k0 += 16) {
        // ---- stage chunk: 128x16 of A and W, split hi/lo ----
        #pragma unroll
        for (int half = 0; half < 2; half++) {
            int row = half * 64 + ldRow0;
            int r = rowBase + row;
            float4 av = (r < Nrows) ? *(const float4*)&A[(size_t)r * K + k0 + ldQ]
                                    : make_float4(0.f,0.f,0.f,0.f);
            float4 h, l;
            h.x = tf32_rna(av.x); l.x = av.x - h.x;
            h.y = tf32_rna(av.y); l.y = av.y - h.y;
            h.z = tf32_rna(av.z); l.z = av.z - h.z;
            h.w = tf32_rna(av.w); l.w = av.w - h.w;
            *(float4*)&Ah[row][ldQ] = h;
            *(float4*)&Al[row][ldQ] = l;
            float4 wv = *(const float4*)&Wt[(size_t)row * K + k0 + ldQ];
            h.x = tf32_rna(wv.x); l.x = wv.x - h.x;
            h.y = tf32_rna(wv.y); l.y = wv.y - h.y;
            h.z = tf32_rna(wv.z); l.z = wv.z - h.z;
            h.w = tf32_rna(wv.w); l.w = wv.w - h.w;
            *(float4*)&Bh[row][ldQ] = h;
            *(float4*)&Bl[row][ldQ] = l;
        }
        __syncthreads();

        // ---- compute: 2 k-steps of 8 ----
        #pragma unroll
        for (int ks = 0; ks < 2; ks++) {
            const int kc = ks * 8;
            uint32_t ah[2][4], al[2][4];
            #pragma unroll
            for (int mf = 0; mf < 2; mf++) {
                int r0 = warpRow + mf * 16 + tq;
                ah[mf][0] = __float_as_uint(Ah[r0    ][kc + tr    ]);
                ah[mf][1] = __float_as_uint(Ah[r0 + 8][kc + tr    ]);
                ah[mf][2] = __float_as_uint(Ah[r0    ][kc + tr + 4]);
                ah[mf][3] = __float_as_uint(Ah[r0 + 8][kc + tr + 4]);
                al[mf][0] = __float_as_uint(Al[r0    ][kc + tr    ]);
                al[mf][1] = __float_as_uint(Al[r0 + 8][kc + tr    ]);
                al[mf][2] = __float_as_uint(Al[r0    ][kc + tr + 4]);
                al[mf][3] = __float_as_uint(Al[r0 + 8][kc + tr + 4]);
            }
            #pragma unroll
            for (int nf = 0; nf < 8; nf++) {
                int c0 = warpCol + nf * 8 + tq;
                uint32_t bh0 = __float_as_uint(Bh[c0][kc + tr    ]);
                uint32_t bh1 = __float_as_uint(Bh[c0][kc + tr + 4]);
                uint32_t bl0 = __float_as_uint(Bl[c0][kc + tr    ]);
                uint32_t bl1 = __float_as_uint(Bl[c0][kc + tr + 4]);
                #pragma unroll
                for (int mf = 0; mf < 2; mf++) {
                    mma_tf32(acc[mf][nf], ah[mf], bh0, bh1);
                    mma_tf32(acc[mf][nf], al[mf], bh0, bh1);
                    mma_tf32(acc[mf][nf], ah[mf], bl0, bl1);
                }
            }
        }
        __syncthreads();
    }

    // ---- epilogue: bias + activation + direct float2 stores ----
    #pragma unroll
    for (int mf = 0; mf < 2; mf++) {
        int r0 = rowBase + warpRow + mf * 16 + tq;
        #pragma unroll
        for (int nf = 0; nf < 8; nf++) {
            int cb = colBase + warpCol + nf * 8 + tr * 2;
            float b0 = bias ? bias[cb] : 0.f;
            float b1 = bias ? bias[cb + 1] : 0.f;
            float v0 = acc[mf][nf][0] + b0;
            float v1 = acc[mf][nf][1] + b1;
            float v2 = acc[mf][nf][2] + b0;
            float v3 = acc[mf][nf][3] + b1;
            if (SILU) {
                v0 = v0 / (1.f + expf(-v0));
                v1 = v1 / (1.f + expf(-v1));
                v2 = v2 / (1.f + expf(-v2));
                v3 = v3 / (1.f + expf(-v3));
            }
            if (r0 < Nrows)      *(float2*)&C[(size_t)r0      * Mcols + cb] = make_float2(v0, v1);
            if (r0 + 8 < Nrows)  *(float2*)&C[(size_t)(r0 + 8) * Mcols + cb] = make_float2(v2, v3);
        }
    }
}

// ---------------- edge message: w_s, inv, scatter-add ----------------
__global__ void edge_msg_kernel(const float* __restrict__ phi,
                                const float* __restrict__ v_old,
                                const float* __restrict__ distW,
                                const float* __restrict__ distb,
                                const int* __restrict__ ei, const int* __restrict__ ej,
                                const float* __restrict__ unit, const float* __restrict__ rbf,
                                const float* __restrict__ env,
                                float* __restrict__ s_acc, float* __restrict__ v_acc) {
    __shared__ float dw[384*21];
    __shared__ float db[384];
    const int tid = threadIdx.x;
    for (int idx = tid; idx < 384*NRBF; idx += 256)
        dw[(idx/NRBF)*21 + (idx%NRBF)] = distW[idx];
    for (int idx = tid; idx < 384; idx += 256) db[idx] = distb[idx];
    __syncthreads();

    const int slot = tid >> 7;   // 0 or 1
    const int f    = tid & 127;
    for (int e = blockIdx.x*2 + slot; e < EDG; e += gridDim.x*2) {
        int i = ei[e], j = ej[e];
        float rb[NRBF];
        #pragma unroll
        for (int k = 0; k < NRBF; k++) rb[k] = rbf[e*NRBF + k];
        float ev = env[e];
        float u0 = unit[e*3+0], u1 = unit[e*3+1], u2 = unit[e*3+2];
        float inv[3];
        #pragma unroll
        for (int c = 0; c < 3; c++) {
            int ch = c*128 + f;
            const float* w = &dw[ch*21];
            float acc = db[ch];
            #pragma unroll
            for (int k = 0; k < NRBF; k++) acc += rb[k] * w[k];
            inv[c] = phi[(size_t)j*384 + ch] * (acc * ev);
        }
        atomicAdd(&s_acc[(size_t)i*128 + f], inv[1]);
        #pragma unroll
        for (int d = 0; d < 3; d++) {
            float vj = v_old[(size_t)d*NF + (size_t)j*128 + f];
            float ud = (d == 0) ? u0 : ((d == 1) ? u1 : u2);
            float dv = inv[2]*ud + inv[0]*vj;
            atomicAdd(&v_acc[(size_t)d*NF + (size_t)i*128 + f], dv);
        }
    }
}

// ---------------- xcat = [s, ||v_v||] ----------------
__global__ void xcat_kernel(const float* __restrict__ s, const float* __restrict__ vv,
                            float* __restrict__ xcat) {
    int idx = blockIdx.x * blockDim.x + threadIdx.x;
    if (idx >= NF) return;
    int n = idx >> 7, f = idx & 127;
    float a = vv[idx], b = vv[NF + idx], c = vv[2*NF + idx];
    xcat[(size_t)n*256 + f]       = s[idx];
    xcat[(size_t)n*256 + 128 + f] = sqrtf(a*a + b*b + c*c);
}

// ---------------- final gated update (in place) ----------------
__global__ void update_kernel(const float* __restrict__ uv, const float* __restrict__ vv,
                              const float* __restrict__ am,
                              float* __restrict__ s, float* __restrict__ v) {
    int idx = blockIdx.x * blockDim.x + threadIdx.x;
    if (idx >= NF) return;
    int n = idx >> 7, f = idx & 127;
    float dot = uv[idx]*vv[idx] + uv[NF+idx]*vv[NF+idx] + uv[2*NF+idx]*vv[2*NF+idx];
    float a0 = am[(size_t)n*384 + f];
    float a1 = am[(size_t)n*384 + 128 + f];
    float a2 = am[(size_t)n*384 + 256 + f];
    s[idx] += dot * a1 + a2;
    #pragma unroll
    for (int d = 0; d < 3; d++)
        v[(size_t)d*NF + idx] += uv[(size_t)d*NF + idx] * a0;
}

// ---------------- pack output: s flat, then v as (N,128,3) ----------------
__global__ void output_kernel(const float* __restrict__ s, const float* __restrict__ v,
                              float* __restrict__ out) {
    int idx = blockIdx.x * blockDim.x + threadIdx.x;
    if (idx >= NF) return;
    int n = idx >> 7, f = idx & 127;
    out[idx] = s[idx];
    #pragma unroll
    for (int d = 0; d < 3; d++)
        out[(size_t)NF + (size_t)n*384 + f*3 + d] = v[(size_t)d*NF + idx];
}

// ---------------- host orchestration ----------------
extern "C" void kernel_launch(void* const* d_in, const int* in_sizes, int n_in,
                              void* d_out, int out_size) {
    const float* xyz    = (const float*)d_in[0];
    const int*   nbr    = (const int*)  d_in[1];
    const float* cg_s   = (const float*)d_in[2];
    const float* msg_W1 = (const float*)d_in[3];
    const float* msg_b1 = (const float*)d_in[4];
    const float* msg_W2 = (const float*)d_in[5];
    const float* msg_b2 = (const float*)d_in[6];
    const float* dist_W = (const float*)d_in[7];
    const float* dist_b = (const float*)d_in[8];
    const float* upd_U  = (const float*)d_in[9];
    const float* upd_V  = (const float*)d_in[10];
    const float* upd_sW1= (const float*)d_in[11];
    const float* upd_sb1= (const float*)d_in[12];
    const float* upd_sW2= (const float*)d_in[13];
    const float* upd_sb2= (const float*)d_in[14];
    float* out = (float*)d_out;

    float *sA, *sB, *vA, *vB, *phi, *hid, *uv, *vv, *xcat, *am, *unit, *rbf, *env;
    int *ei, *ej;
    cudaGetSymbolAddress((void**)&sA,   g_sA);
    cudaGetSymbolAddress((void**)&sB,   g_sB);
    cudaGetSymbolAddress((void**)&vA,   g_vA);
    cudaGetSymbolAddress((void**)&vB,   g_vB);
    cudaGetSymbolAddress((void**)&phi,  g_phi);
    cudaGetSymbolAddress((void**)&hid,  g_hid);
    cudaGetSymbolAddress((void**)&uv,   g_uv);
    cudaGetSymbolAddress((void**)&vv,   g_vv);
    cudaGetSymbolAddress((void**)&xcat, g_xcat);
    cudaGetSymbolAddress((void**)&am,   g_am);
    cudaGetSymbolAddress((void**)&unit, g_unit);
    cudaGetSymbolAddress((void**)&rbf,  g_rbf);
    cudaGetSymbolAddress((void**)&env,  g_env);
    cudaGetSymbolAddress((void**)&ei,   g_ei);
    cudaGetSymbolAddress((void**)&ej,   g_ej);

    const int TPB = 256;
    copy4_kernel<<<(NF/4 + TPB-1)/TPB, TPB>>>((float4*)sA, (const float4*)cg_s, NF/4);
    zero4_kernel<<<(3*NF/4 + TPB-1)/TPB, TPB>>>((float4*)vA, 3*NF/4);
    edge_geom_kernel<<<(EDG + TPB-1)/TPB, TPB>>>(xyz, nbr, unit, rbf, env, ei, ej);

    const int RT = (NN + 127) / 128;   // 157 row tiles
    float* s_cur = sA; float* s_nxt = sB;
    float* v_cur = vA; float* v_nxt = vB;

    for (int l = 0; l < NCONV; l++) {
        // phi = silu(s @ W1^T + b1) @ W2^T + b2
        mma_gemm_kernel<true ><<<dim3(1, RT, 1), TPB>>>(
            s_cur, 0, msg_W1 + (size_t)l*FEAT*FEAT, msg_b1 + (size_t)l*FEAT,
            hid, 0, NN, FEAT, FEAT);
        mma_gemm_kernel<false><<<dim3(3, RT, 1), TPB>>>(
            hid, 0, msg_W2 + (size_t)l*384*FEAT, msg_b2 + (size_t)l*384,
            phi, 0, NN, 384, FEAT);
        // accumulators = current state
        copy4_kernel<<<(NF/4 + TPB-1)/TPB, TPB>>>((float4*)s_nxt, (const float4*)s_cur, NF/4);
        copy4_kernel<<<(3*NF/4 + TPB-1)/TPB, TPB>>>((float4*)v_nxt, (const float4*)v_cur, 3*NF/4);
        // edge messages + scatter
        edge_msg_kernel<<<1184, TPB>>>(phi, v_cur,
                                       dist_W + (size_t)l*384*NRBF, dist_b + (size_t)l*384,
                                       ei, ej, unit, rbf, env, s_nxt, v_nxt);
        // u_v, v_v (batched over 3 spatial dims)
        mma_gemm_kernel<false><<<dim3(1, RT, 3), TPB>>>(
            v_nxt, (size_t)NF, upd_U + (size_t)l*FEAT*FEAT, nullptr,
            uv, (size_t)NF, NN, FEAT, FEAT);
        mma_gemm_kernel<false><<<dim3(1, RT, 3), TPB>>>(
            v_nxt, (size_t)NF, upd_V + (size_t)l*FEAT*FEAT, nullptr,
            vv, (size_t)NF, NN, FEAT, FEAT);
        // xcat = [s, ||v_v||]
        xcat_kernel<<<(NF + TPB-1)/TPB, TPB>>>(s_nxt, vv, xcat);
        // a = silu(xcat @ sW1^T + sb1) @ sW2^T + sb2
        mma_gemm_kernel<true ><<<dim3(1, RT, 1), TPB>>>(
            xcat, 0, upd_sW1 + (size_t)l*FEAT*256, upd_sb1 + (size_t)l*FEAT,
            hid, 0, NN, FEAT, 256);
        mma_gemm_kernel<false><<<dim3(3, RT, 1), TPB>>>(
            hid, 0, upd_sW2 + (size_t)l*384*FEAT, upd_sb2 + (size_t)l*384,
            am, 0, NN, 384, FEAT);
        // gated update
        update_kernel<<<(NF + TPB-1)/TPB, TPB>>>(uv, vv, am, s_nxt, v_nxt);

        float* t;
        t = s_cur; s_cur = s_nxt; s_nxt = t;
        t = v_cur; v_cur = v_nxt; v_nxt = t;
    }

    output_kernel<<<(NF + TPB-1)/TPB, TPB>>>(s_cur, v_cur, out);
}